// round 1
// baseline (speedup 1.0000x reference)
#include <cuda_runtime.h>

#define NQ   10
#define DIM  1024
#define NL   4
#define BATCH 4096
#define SEQ  512
#define PRED 96

// ---------------- device scratch (allocation-free) ----------------
__device__ float  g_h[BATCH * DIM];          // 16 MB intermediate h
__device__ float2 g_gates[NL * NQ * 4];      // 40 gates x 4 complex entries
__device__ int    g_perm[NL * DIM];          // 4 layer permutations

// ---------------- kernel 1: precompute gates + perms ----------------
__global__ void precompute_kernel(const float* __restrict__ qw) {
    int t = threadIdx.x;
    if (t < NL * NQ) {
        float phi   = qw[3 * t + 0];
        float theta = qw[3 * t + 1];
        float omega = qw[3 * t + 2];
        float s, c;
        sincosf(0.5f * theta, &s, &c);
        float a = 0.5f * (phi + omega);
        float b = 0.5f * (phi - omega);
        float sa, ca, sb, cb;
        sincosf(a, &sa, &ca);
        sincosf(b, &sb, &cb);
        // m00 = conj(e^{ia}) * c ; m01 = -e^{ib} * s ; m10 = conj(e^{ib}) * s ; m11 = e^{ia} * c
        g_gates[4 * t + 0] = make_float2( c * ca, -c * sa);
        g_gates[4 * t + 1] = make_float2(-s * cb, -s * sb);
        g_gates[4 * t + 2] = make_float2( s * cb, -s * sb);
        g_gates[4 * t + 3] = make_float2( c * ca,  c * sa);
    }
    if (t < DIM) {
        for (int l = 0; l < NL; l++) {
            int r = l % (NQ - 1) + 1;
            int p = t;
            // PERM[s] = g_0(g_1(...g_{NQ-1}(s)...)): apply g_{NQ-1} first
            for (int c = NQ - 1; c >= 0; c--) {
                int bit = (p >> (NQ - 1 - c)) & 1;
                int tgt = (c + r) % NQ;
                p ^= bit << (NQ - 1 - tgt);
            }
            g_perm[l * DIM + t] = p;
        }
    }
}

// ---------------- kernel 2: h = x @ W_in^T + b_in + 1e-6 ----------------
#define BM 64
#define BN 64
#define BK 16

__global__ __launch_bounds__(256) void gemm_kernel(const float* __restrict__ x,
                                                   const float* __restrict__ W,
                                                   const float* __restrict__ bias) {
    __shared__ float As[BK][BM];
    __shared__ float Bs[BK][BN];
    const int tid = threadIdx.x;
    const int bm = blockIdx.y * BM;     // batch offset
    const int bn = blockIdx.x * BN;     // dim offset
    const int row = tid >> 2;           // 0..63
    const int kq  = (tid & 3) << 2;     // 0,4,8,12
    const int tm  = (tid >> 4) << 2;    // 0..60
    const int tn  = (tid & 15) << 2;    // 0..60

    float acc[4][4];
#pragma unroll
    for (int i = 0; i < 4; i++)
#pragma unroll
        for (int j = 0; j < 4; j++) acc[i][j] = 0.f;

    for (int k0 = 0; k0 < SEQ; k0 += BK) {
        float4 av = *(const float4*)(x + (size_t)(bm + row) * SEQ + k0 + kq);
        float4 bv = *(const float4*)(W + (size_t)(bn + row) * SEQ + k0 + kq);
        As[kq + 0][row] = av.x; As[kq + 1][row] = av.y;
        As[kq + 2][row] = av.z; As[kq + 3][row] = av.w;
        Bs[kq + 0][row] = bv.x; Bs[kq + 1][row] = bv.y;
        Bs[kq + 2][row] = bv.z; Bs[kq + 3][row] = bv.w;
        __syncthreads();
#pragma unroll
        for (int kk = 0; kk < BK; kk++) {
            float4 a4 = *(const float4*)&As[kk][tm];
            float4 b4 = *(const float4*)&Bs[kk][tn];
            float a[4] = {a4.x, a4.y, a4.z, a4.w};
            float b[4] = {b4.x, b4.y, b4.z, b4.w};
#pragma unroll
            for (int i = 0; i < 4; i++)
#pragma unroll
                for (int j = 0; j < 4; j++) acc[i][j] += a[i] * b[j];
        }
        __syncthreads();
    }

    float4 bb = *(const float4*)(bias + bn + tn);
    bb.x += 1e-6f; bb.y += 1e-6f; bb.z += 1e-6f; bb.w += 1e-6f;
#pragma unroll
    for (int i = 0; i < 4; i++) {
        float4 o;
        o.x = acc[i][0] + bb.x;
        o.y = acc[i][1] + bb.y;
        o.z = acc[i][2] + bb.z;
        o.w = acc[i][3] + bb.w;
        *(float4*)(g_h + (size_t)(bm + tm + i) * DIM + bn + tn) = o;
    }
}

// ---------------- kernel 3: normalize + circuit + expvals + out proj ----------------
__global__ __launch_bounds__(512) void circuit_kernel(const float* __restrict__ Wout,
                                                      const float* __restrict__ bout,
                                                      float* __restrict__ out) {
    __shared__ float  sre[2][DIM];
    __shared__ float  sim[2][DIM];
    __shared__ float2 sg[NL * NQ * 4];
    __shared__ float  swred[16][NQ];
    __shared__ float  sev[NQ];
    __shared__ float  sred[16];

    const int tid = threadIdx.x;
    const int b   = blockIdx.x;
    const float* hrow = g_h + (size_t)b * DIM;

    float h0 = hrow[tid];
    float h1 = hrow[tid + 512];
    if (tid < NL * NQ * 4) sg[tid] = g_gates[tid];

    // row norm (deterministic: shfl tree + sequential 16-sum)
    float ss = h0 * h0 + h1 * h1;
#pragma unroll
    for (int o = 16; o; o >>= 1) ss += __shfl_xor_sync(0xffffffffu, ss, o);
    if ((tid & 31) == 0) sred[tid >> 5] = ss;
    __syncthreads();
    if (tid == 0) {
        float t = 0.f;
#pragma unroll
        for (int i = 0; i < 16; i++) t += sred[i];
        sred[0] = rsqrtf(t);
    }
    __syncthreads();
    float inv = sred[0];

    int cur = 0;
    sre[0][tid]       = h0 * inv;
    sre[0][tid + 512] = h1 * inv;
    sim[0][tid]       = 0.f;
    sim[0][tid + 512] = 0.f;
    __syncthreads();

    for (int l = 0; l < NL; l++) {
#pragma unroll
        for (int w = 0; w < NQ; w++) {
            const float2 u00 = sg[(l * NQ + w) * 4 + 0];
            const float2 u01 = sg[(l * NQ + w) * 4 + 1];
            const float2 u10 = sg[(l * NQ + w) * 4 + 2];
            const float2 u11 = sg[(l * NQ + w) * 4 + 3];
            const int m  = NQ - 1 - w;                 // acted bit (from LSB)
            const int lo = ((tid >> m) << (m + 1)) | (tid & ((1 << m) - 1));
            const int hi = lo | (1 << m);
            float ar = sre[cur][lo], ai = sim[cur][lo];
            float br = sre[cur][hi], bi = sim[cur][hi];
            float nar = u00.x * ar - u00.y * ai + u01.x * br - u01.y * bi;
            float nai = u00.x * ai + u00.y * ar + u01.x * bi + u01.y * br;
            float nbr = u10.x * ar - u10.y * ai + u11.x * br - u11.y * bi;
            float nbi = u10.x * ai + u10.y * ar + u11.x * bi + u11.y * br;
            sre[cur][lo] = nar; sim[cur][lo] = nai;
            sre[cur][hi] = nbr; sim[cur][hi] = nbi;
            __syncthreads();
        }
        // layer permutation: psi_new[k] = psi[perm[k]] (ping-pong)
        const int* pm = g_perm + l * DIM;
        int p0 = __ldg(pm + tid);
        int p1 = __ldg(pm + tid + 512);
        sre[cur ^ 1][tid]       = sre[cur][p0];
        sim[cur ^ 1][tid]       = sim[cur][p0];
        sre[cur ^ 1][tid + 512] = sre[cur][p1];
        sim[cur ^ 1][tid + 512] = sim[cur][p1];
        cur ^= 1;
        __syncthreads();
    }

    // expvals[q] = sum_k probs[k] * (1 - 2*bit_q(k))
    float acc[NQ];
#pragma unroll
    for (int q = 0; q < NQ; q++) acc[q] = 0.f;
#pragma unroll
    for (int half = 0; half < 2; half++) {
        int k = tid + half * 512;
        float r = sre[cur][k], im = sim[cur][k];
        float p = r * r + im * im;
#pragma unroll
        for (int q = 0; q < NQ; q++)
            acc[q] += ((k >> (NQ - 1 - q)) & 1) ? -p : p;
    }
#pragma unroll
    for (int q = 0; q < NQ; q++) {
#pragma unroll
        for (int o = 16; o; o >>= 1) acc[q] += __shfl_xor_sync(0xffffffffu, acc[q], o);
    }
    if ((tid & 31) == 0) {
        int wi = tid >> 5;
#pragma unroll
        for (int q = 0; q < NQ; q++) swred[wi][q] = acc[q];
    }
    __syncthreads();
    if (tid < NQ) {
        float e = 0.f;
#pragma unroll
        for (int w = 0; w < 16; w++) e += swred[w][tid];
        sev[tid] = e;
    }
    __syncthreads();
    if (tid < PRED) {
        float o = bout[tid];
#pragma unroll
        for (int q = 0; q < NQ; q++) o += sev[q] * Wout[tid * NQ + q];
        out[(size_t)b * PRED + tid] = o;
    }
}

// ---------------- launch ----------------
extern "C" void kernel_launch(void* const* d_in, const int* in_sizes, int n_in,
                              void* d_out, int out_size) {
    const float* x     = (const float*)d_in[0];
    const float* W_in  = (const float*)d_in[1];
    const float* b_in  = (const float*)d_in[2];
    const float* qw    = (const float*)d_in[3];
    const float* W_out = (const float*)d_in[4];
    const float* b_out = (const float*)d_in[5];
    float* out = (float*)d_out;

    precompute_kernel<<<1, 1024>>>(qw);
    dim3 grid(DIM / BN, BATCH / BM);
    gemm_kernel<<<grid, 256>>>(x, W_in, b_in);
    circuit_kernel<<<BATCH, 512>>>(W_out, b_out, out);
}

// round 2
// speedup vs baseline: 2.3382x; 2.3382x over previous
#include <cuda_runtime.h>
#include <cstdint>

#define NQ    10
#define DIM   1024
#define NL    4
#define BATCH 4096
#define SEQ   512
#define PRED  96

// ---------------- device scratch (allocation-free) ----------------
__device__ float  g_h[BATCH * DIM];            // 16 MB intermediate h
__device__ float  g_xhi[BATCH * SEQ];
__device__ float  g_xlo[BATCH * SEQ];
__device__ float  g_whi[DIM * SEQ];
__device__ float  g_wlo[DIM * SEQ];
__device__ float2 g_gates[NL * NQ * 4];
__device__ int    g_perm[NL * DIM];

__device__ __forceinline__ float tf32r(float v) {
    unsigned u;
    asm("cvt.rna.tf32.f32 %0, %1;" : "=r"(u) : "f"(v));
    return __uint_as_float(u);
}

// ---------------- kernel 0: tf32 hi/lo split of x and W ----------------
__global__ void split_kernel(const float* __restrict__ x, const float* __restrict__ w) {
    int i = blockIdx.x * blockDim.x + threadIdx.x;
    if (i < BATCH * SEQ) {
        float v = x[i];
        float h = tf32r(v);
        g_xhi[i] = h;
        g_xlo[i] = tf32r(v - h);
    }
    if (i < DIM * SEQ) {
        float v = w[i];
        float h = tf32r(v);
        g_whi[i] = h;
        g_wlo[i] = tf32r(v - h);
    }
}

// ---------------- kernel 1: precompute gates + perms ----------------
__global__ void precompute_kernel(const float* __restrict__ qw) {
    int t = threadIdx.x;
    if (t < NL * NQ) {
        float phi   = qw[3 * t + 0];
        float theta = qw[3 * t + 1];
        float omega = qw[3 * t + 2];
        float s, c;
        sincosf(0.5f * theta, &s, &c);
        float a = 0.5f * (phi + omega);
        float b = 0.5f * (phi - omega);
        float sa, ca, sb, cb;
        sincosf(a, &sa, &ca);
        sincosf(b, &sb, &cb);
        g_gates[4 * t + 0] = make_float2( c * ca, -c * sa);
        g_gates[4 * t + 1] = make_float2(-s * cb, -s * sb);
        g_gates[4 * t + 2] = make_float2( s * cb, -s * sb);
        g_gates[4 * t + 3] = make_float2( c * ca,  c * sa);
    }
    if (t < DIM) {
        for (int l = 0; l < NL; l++) {
            int r = l % (NQ - 1) + 1;
            int p = t;
            for (int c = NQ - 1; c >= 0; c--) {
                int bit = (p >> (NQ - 1 - c)) & 1;
                int tgt = (c + r) % NQ;
                p ^= bit << (NQ - 1 - tgt);
            }
            g_perm[l * DIM + t] = p;
        }
    }
}

// ---------------- kernel 2: tensor-core GEMM (3xTF32) ----------------
#define GBM 128
#define GBN 128
#define GBK 16
#define LDA 20   // GBK + 4 pad -> conflict-free frag reads

#define MMA_TF32(C, A, B)                                                       \
    asm volatile("mma.sync.aligned.m16n8k8.row.col.f32.tf32.tf32.f32 "          \
                 "{%0,%1,%2,%3}, {%4,%5,%6,%7}, {%8,%9}, {%0,%1,%2,%3};"        \
                 : "+f"((C)[0]), "+f"((C)[1]), "+f"((C)[2]), "+f"((C)[3])       \
                 : "r"((A)[0]), "r"((A)[1]), "r"((A)[2]), "r"((A)[3]),          \
                   "r"((B)[0]), "r"((B)[1]))

__global__ __launch_bounds__(256) void gemm_tc(const float* __restrict__ bias) {
    __shared__ float sA[2][GBM * LDA];
    __shared__ float sB[2][GBN * LDA];
    const int tid  = threadIdx.x;
    const int lane = tid & 31, wid = tid >> 5;
    const int wm = wid >> 2, wn = wid & 3;        // warps: 2(m) x 4(n); warp tile 64x32
    const int bm = blockIdx.y * GBM, bn = blockIdx.x * GBN;
    const int g = lane >> 2, tg = lane & 3;

    float c[4][4][4];
#pragma unroll
    for (int mi = 0; mi < 4; mi++)
#pragma unroll
        for (int ni = 0; ni < 4; ni++)
#pragma unroll
            for (int k = 0; k < 4; k++) c[mi][ni][k] = 0.f;

    const int r_ld = tid >> 2;                 // rows 0..63 (j=0), 64..127 (j=1)
    const int q_ld = (tid & 3) << 2;           // float4 column offset

    for (int k0 = 0; k0 < SEQ; k0 += GBK) {
#pragma unroll
        for (int j = 0; j < 2; j++) {
            int r = r_ld + j * 64;
            *(float4*)&sA[0][r * LDA + q_ld] =
                *(const float4*)(g_xhi + (size_t)(bm + r) * SEQ + k0 + q_ld);
            *(float4*)&sA[1][r * LDA + q_ld] =
                *(const float4*)(g_xlo + (size_t)(bm + r) * SEQ + k0 + q_ld);
            *(float4*)&sB[0][r * LDA + q_ld] =
                *(const float4*)(g_whi + (size_t)(bn + r) * SEQ + k0 + q_ld);
            *(float4*)&sB[1][r * LDA + q_ld] =
                *(const float4*)(g_wlo + (size_t)(bn + r) * SEQ + k0 + q_ld);
        }
        __syncthreads();

        const unsigned* uA0 = (const unsigned*)sA[0];
        const unsigned* uA1 = (const unsigned*)sA[1];
        const unsigned* uB0 = (const unsigned*)sB[0];
        const unsigned* uB1 = (const unsigned*)sB[1];

#pragma unroll
        for (int kk = 0; kk < GBK; kk += 8) {
            unsigned ah[4][4], al[4][4], bh[4][2], bl[4][2];
#pragma unroll
            for (int mi = 0; mi < 4; mi++) {
                int row  = wm * 64 + mi * 16 + g;
                int base = row * LDA + kk + tg;
                ah[mi][0] = uA0[base];
                ah[mi][1] = uA0[base + 8 * LDA];
                ah[mi][2] = uA0[base + 4];
                ah[mi][3] = uA0[base + 8 * LDA + 4];
                al[mi][0] = uA1[base];
                al[mi][1] = uA1[base + 8 * LDA];
                al[mi][2] = uA1[base + 4];
                al[mi][3] = uA1[base + 8 * LDA + 4];
            }
#pragma unroll
            for (int ni = 0; ni < 4; ni++) {
                int col  = wn * 32 + ni * 8 + g;
                int base = col * LDA + kk + tg;
                bh[ni][0] = uB0[base];
                bh[ni][1] = uB0[base + 4];
                bl[ni][0] = uB1[base];
                bl[ni][1] = uB1[base + 4];
            }
#pragma unroll
            for (int mi = 0; mi < 4; mi++)
#pragma unroll
                for (int ni = 0; ni < 4; ni++) {
                    MMA_TF32(c[mi][ni], ah[mi], bh[ni]);
                    MMA_TF32(c[mi][ni], ah[mi], bl[ni]);
                    MMA_TF32(c[mi][ni], al[mi], bh[ni]);
                }
        }
        __syncthreads();
    }

#pragma unroll
    for (int mi = 0; mi < 4; mi++) {
        int r0 = bm + wm * 64 + mi * 16 + g;
#pragma unroll
        for (int ni = 0; ni < 4; ni++) {
            int cc = bn + wn * 32 + ni * 8 + 2 * tg;
            float b0 = bias[cc] + 1e-6f;
            float b1 = bias[cc + 1] + 1e-6f;
            g_h[(size_t)r0 * DIM + cc]           = c[mi][ni][0] + b0;
            g_h[(size_t)r0 * DIM + cc + 1]       = c[mi][ni][1] + b1;
            g_h[(size_t)(r0 + 8) * DIM + cc]     = c[mi][ni][2] + b0;
            g_h[(size_t)(r0 + 8) * DIM + cc + 1] = c[mi][ni][3] + b1;
        }
    }
}

// ---------------- kernel 3: register-resident circuit ----------------
__global__ __launch_bounds__(512) void circuit_kernel(const float* __restrict__ Wout,
                                                      const float* __restrict__ bout,
                                                      float* __restrict__ out) {
    __shared__ float4 buf[512];       // cross-warp gate exchange
    __shared__ float2 amp[DIM];       // layer permutation staging
    __shared__ float2 sg[NL * NQ * 4];
    __shared__ float  swred[16][NQ];
    __shared__ float  sev[NQ];
    __shared__ float  sred[16];

    const int tid = threadIdx.x;
    const int b   = blockIdx.x;
    const float* hrow = g_h + (size_t)b * DIM;

    float2 hv = *(const float2*)(hrow + 2 * tid);
    if (tid < NL * NQ * 4) sg[tid] = g_gates[tid];

    // row norm (deterministic)
    float ss = hv.x * hv.x + hv.y * hv.y;
#pragma unroll
    for (int o = 16; o; o >>= 1) ss += __shfl_xor_sync(0xffffffffu, ss, o);
    if ((tid & 31) == 0) sred[tid >> 5] = ss;
    __syncthreads();
    if (tid == 0) {
        float t = 0.f;
#pragma unroll
        for (int i = 0; i < 16; i++) t += sred[i];
        sred[0] = rsqrtf(t);
    }
    __syncthreads();
    float inv = sred[0];

    // thread holds amplitudes k = 2*tid (amp0) and 2*tid+1 (amp1)
    float ar0 = hv.x * inv, ai0 = 0.f;
    float ar1 = hv.y * inv, ai1 = 0.f;

    for (int l = 0; l < NL; l++) {
#pragma unroll
        for (int w = 0; w < NQ; w++) {
            const int m = NQ - 1 - w;                 // acted bit (LSB index)
            const float2 u00 = sg[(l * NQ + w) * 4 + 0];
            const float2 u01 = sg[(l * NQ + w) * 4 + 1];
            const float2 u10 = sg[(l * NQ + w) * 4 + 2];
            const float2 u11 = sg[(l * NQ + w) * 4 + 3];
            if (m == 0) {
                // local pair (amp0 = lo, amp1 = hi)
                float nr0 = u00.x * ar0 - u00.y * ai0 + u01.x * ar1 - u01.y * ai1;
                float ni0 = u00.x * ai0 + u00.y * ar0 + u01.x * ai1 + u01.y * ar1;
                float nr1 = u10.x * ar0 - u10.y * ai0 + u11.x * ar1 - u11.y * ai1;
                float ni1 = u10.x * ai0 + u10.y * ar0 + u11.x * ai1 + u11.y * ar1;
                ar0 = nr0; ai0 = ni0; ar1 = nr1; ai1 = ni1;
            } else {
                const int sh = m - 1;
                float or0, oi0, or1, oi1;
                if (m <= 5) {
                    const int msk = 1 << sh;
                    or0 = __shfl_xor_sync(0xffffffffu, ar0, msk);
                    oi0 = __shfl_xor_sync(0xffffffffu, ai0, msk);
                    or1 = __shfl_xor_sync(0xffffffffu, ar1, msk);
                    oi1 = __shfl_xor_sync(0xffffffffu, ai1, msk);
                } else {
                    buf[tid] = make_float4(ar0, ai0, ar1, ai1);
                    __syncthreads();
                    float4 o = buf[tid ^ (1 << sh)];
                    __syncthreads();
                    or0 = o.x; oi0 = o.y; or1 = o.z; oi1 = o.w;
                }
                // branchless: va = coeff of mine, vb = coeff of partner
                const bool hibit = (tid >> sh) & 1;
                const float2 va = hibit ? u11 : u00;
                const float2 vb = hibit ? u10 : u01;
                float nr0 = va.x * ar0 - va.y * ai0 + vb.x * or0 - vb.y * oi0;
                float ni0 = va.x * ai0 + va.y * ar0 + vb.x * oi0 + vb.y * or0;
                float nr1 = va.x * ar1 - va.y * ai1 + vb.x * or1 - vb.y * oi1;
                float ni1 = va.x * ai1 + va.y * ar1 + vb.x * oi1 + vb.y * or1;
                ar0 = nr0; ai0 = ni0; ar1 = nr1; ai1 = ni1;
            }
        }
        // layer permutation: psi_new[k] = psi[perm[k]]
        amp[2 * tid]     = make_float2(ar0, ai0);
        amp[2 * tid + 1] = make_float2(ar1, ai1);
        __syncthreads();
        const int* pm = g_perm + l * DIM;
        int p0 = __ldg(pm + 2 * tid);
        int p1 = __ldg(pm + 2 * tid + 1);
        float2 n0 = amp[p0];
        float2 n1 = amp[p1];
        __syncthreads();
        ar0 = n0.x; ai0 = n0.y; ar1 = n1.x; ai1 = n1.y;
    }

    // expvals: k0 = 2*tid (bit0 = 0), k1 = 2*tid+1 (bit0 = 1); bit0 <-> qubit 9
    float p0 = ar0 * ar0 + ai0 * ai0;
    float p1 = ar1 * ar1 + ai1 * ai1;
    float ps = p0 + p1;
    float acc[NQ];
#pragma unroll
    for (int q = 0; q < NQ - 1; q++)
        acc[q] = ((tid >> (8 - q)) & 1) ? -ps : ps;
    acc[NQ - 1] = p0 - p1;
#pragma unroll
    for (int q = 0; q < NQ; q++) {
#pragma unroll
        for (int o = 16; o; o >>= 1) acc[q] += __shfl_xor_sync(0xffffffffu, acc[q], o);
    }
    if ((tid & 31) == 0) {
        int wi = tid >> 5;
#pragma unroll
        for (int q = 0; q < NQ; q++) swred[wi][q] = acc[q];
    }
    __syncthreads();
    if (tid < NQ) {
        float e = 0.f;
#pragma unroll
        for (int w = 0; w < 16; w++) e += swred[w][tid];
        sev[tid] = e;
    }
    __syncthreads();
    if (tid < PRED) {
        float o = bout[tid];
#pragma unroll
        for (int q = 0; q < NQ; q++) o += sev[q] * Wout[tid * NQ + q];
        out[(size_t)b * PRED + tid] = o;
    }
}

// ---------------- launch ----------------
extern "C" void kernel_launch(void* const* d_in, const int* in_sizes, int n_in,
                              void* d_out, int out_size) {
    const float* x     = (const float*)d_in[0];
    const float* W_in  = (const float*)d_in[1];
    const float* b_in  = (const float*)d_in[2];
    const float* qw    = (const float*)d_in[3];
    const float* W_out = (const float*)d_in[4];
    const float* b_out = (const float*)d_in[5];
    float* out = (float*)d_out;

    split_kernel<<<(BATCH * SEQ + 255) / 256, 256>>>(x, W_in);
    precompute_kernel<<<1, 1024>>>(qw);
    dim3 grid(DIM / GBN, BATCH / GBM);
    gemm_tc<<<grid, 256>>>(b_in);
    circuit_kernel<<<BATCH, 512>>>(W_out, b_out, out);
}

// round 6
// speedup vs baseline: 3.5145x; 1.5031x over previous
#include <cuda_runtime.h>
#include <cuda_bf16.h>
#include <cstdint>

#define NQ    10
#define DIM   1024
#define NL    4
#define BATCH 4096
#define SEQ   512
#define PRED  96

// ---------------- device scratch (allocation-free) ----------------
__device__ float         g_h[BATCH * DIM];       // 16 MB intermediate h
__device__ __nv_bfloat16 g_xhi[BATCH * SEQ];
__device__ __nv_bfloat16 g_xlo[BATCH * SEQ];
__device__ __nv_bfloat16 g_whi[DIM * SEQ];
__device__ __nv_bfloat16 g_wlo[DIM * SEQ];
__device__ float2        g_gates[NL * NQ * 4];
__device__ int           g_perm[NL * DIM];

// ---------------- kernel 0: bf16 hi/lo split of x and W ----------------
__global__ void split_kernel(const float* __restrict__ x, const float* __restrict__ w) {
    int i = blockIdx.x * blockDim.x + threadIdx.x;
    if (i < BATCH * SEQ) {
        float v = x[i];
        __nv_bfloat16 h = __float2bfloat16(v);
        g_xhi[i] = h;
        g_xlo[i] = __float2bfloat16(v - __bfloat162float(h));
    }
    if (i < DIM * SEQ) {
        float v = w[i];
        __nv_bfloat16 h = __float2bfloat16(v);
        g_whi[i] = h;
        g_wlo[i] = __float2bfloat16(v - __bfloat162float(h));
    }
}

// ---------------- kernel 1: precompute gates + perms ----------------
__global__ void precompute_kernel(const float* __restrict__ qw) {
    int t = threadIdx.x;
    if (t < NL * NQ) {
        float phi   = qw[3 * t + 0];
        float theta = qw[3 * t + 1];
        float omega = qw[3 * t + 2];
        float s, c;
        sincosf(0.5f * theta, &s, &c);
        float a = 0.5f * (phi + omega);
        float b = 0.5f * (phi - omega);
        float sa, ca, sb, cb;
        sincosf(a, &sa, &ca);
        sincosf(b, &sb, &cb);
        g_gates[4 * t + 0] = make_float2( c * ca, -c * sa);
        g_gates[4 * t + 1] = make_float2(-s * cb, -s * sb);
        g_gates[4 * t + 2] = make_float2( s * cb, -s * sb);
        g_gates[4 * t + 3] = make_float2( c * ca,  c * sa);
    }
    if (t < DIM) {
        for (int l = 0; l < NL; l++) {
            int r = l % (NQ - 1) + 1;
            int p = t;
            for (int c = NQ - 1; c >= 0; c--) {
                int bit = (p >> (NQ - 1 - c)) & 1;
                int tgt = (c + r) % NQ;
                p ^= bit << (NQ - 1 - tgt);
            }
            g_perm[l * DIM + t] = p;
        }
    }
}

// ---------------- kernel 2: bf16 tensor-core GEMM (3-product) ----------------
#define GBM 128
#define GBN 128
#define GBK 16
#define SROW 24                 // bf16 per smem row (16 + 8 pad) = 48 bytes
#define MATB (GBM * SROW * 2)   // bytes per matrix tile = 6144
#define STAGEB (4 * MATB)       // bytes per stage = 24576

#define MMA_BF16(C, A, B)                                                       \
    asm volatile("mma.sync.aligned.m16n8k16.row.col.f32.bf16.bf16.f32 "         \
                 "{%0,%1,%2,%3}, {%4,%5,%6,%7}, {%8,%9}, {%0,%1,%2,%3};"        \
                 : "+f"((C)[0]), "+f"((C)[1]), "+f"((C)[2]), "+f"((C)[3])       \
                 : "r"((A)[0]), "r"((A)[1]), "r"((A)[2]), "r"((A)[3]),          \
                   "r"((B)[0]), "r"((B)[1]))

#define LDM4(R, addr)                                                           \
    asm volatile("ldmatrix.sync.aligned.m8n8.x4.shared.b16 {%0,%1,%2,%3},[%4];" \
                 : "=r"((R)[0]), "=r"((R)[1]), "=r"((R)[2]), "=r"((R)[3])       \
                 : "r"(addr))

#define CPASYNC16(dst, src)                                                     \
    asm volatile("cp.async.cg.shared.global [%0], [%1], 16;" ::                 \
                 "r"(dst), "l"(src))

__global__ __launch_bounds__(256) void gemm_tc(const float* __restrict__ bias) {
    __shared__ __nv_bfloat16 smem[2 * 4 * GBM * SROW];   // 49152 bytes
    const int tid  = threadIdx.x;
    const int lane = tid & 31, wid = tid >> 5;
    const int wm = wid >> 2, wn = wid & 3;               // 2(m) x 4(n) warps; warp tile 64x32
    const int bm = blockIdx.y * GBM, bn = blockIdx.x * GBN;
    const int g = lane >> 2, tg = lane & 3;

    const uint32_t sbase = (uint32_t)__cvta_generic_to_shared(smem);

    float c[4][4][4];
#pragma unroll
    for (int mi = 0; mi < 4; mi++)
#pragma unroll
        for (int ni = 0; ni < 4; ni++)
#pragma unroll
            for (int k = 0; k < 4; k++) c[mi][ni][k] = 0.f;

    // loader indexing: 256 threads, each does one 16B chunk per matrix
    const int lr = tid >> 1, lc = tid & 1;
    const size_t offA = (size_t)(bm + lr) * SEQ + lc * 8;
    const size_t offB = (size_t)(bn + lr) * SEQ + lc * 8;
    const uint32_t ldst = (uint32_t)(lr * SROW + lc * 8) * 2;

    auto load_stage = [&](int st, int k0) {
        uint32_t d = sbase + st * STAGEB + ldst;
        CPASYNC16(d + 0 * MATB, g_xhi + offA + k0);
        CPASYNC16(d + 1 * MATB, g_xlo + offA + k0);
        CPASYNC16(d + 2 * MATB, g_whi + offB + k0);
        CPASYNC16(d + 3 * MATB, g_wlo + offB + k0);
        asm volatile("cp.async.commit_group;");
    };

    const int rA   = (lane & 7) + ((lane >> 3) & 1) * 8;
    const int colo = (lane >> 4) * 16;

    load_stage(0, 0);
    const int NIT = SEQ / GBK;
    for (int it = 0; it < NIT; it++) {
        if (it + 1 < NIT) {
            load_stage((it + 1) & 1, (it + 1) * GBK);
            asm volatile("cp.async.wait_group 1;");
        } else {
            asm volatile("cp.async.wait_group 0;");
        }
        __syncthreads();

        const uint32_t st = sbase + (it & 1) * STAGEB;
        unsigned ah[4][4], al[4][4], bh[4][2], bl[4][2];
#pragma unroll
        for (int mi = 0; mi < 4; mi++) {
            uint32_t ad = st + (uint32_t)((wm * 64 + mi * 16 + rA) * SROW) * 2 + colo;
            LDM4(ah[mi], ad);
            LDM4(al[mi], ad + MATB);
        }
#pragma unroll
        for (int nj = 0; nj < 2; nj++) {
            uint32_t bd = st + 2 * MATB + (uint32_t)((wn * 32 + nj * 16 + rA) * SROW) * 2 + colo;
            unsigned r[4];
            LDM4(r, bd);
            bh[2 * nj][0] = r[0]; bh[2 * nj + 1][0] = r[1];
            bh[2 * nj][1] = r[2]; bh[2 * nj + 1][1] = r[3];
            LDM4(r, bd + MATB);
            bl[2 * nj][0] = r[0]; bl[2 * nj + 1][0] = r[1];
            bl[2 * nj][1] = r[2]; bl[2 * nj + 1][1] = r[3];
        }
#pragma unroll
        for (int mi = 0; mi < 4; mi++)
#pragma unroll
            for (int ni = 0; ni < 4; ni++) {
                MMA_BF16(c[mi][ni], ah[mi], bh[ni]);
                MMA_BF16(c[mi][ni], ah[mi], bl[ni]);
                MMA_BF16(c[mi][ni], al[mi], bh[ni]);
            }
        __syncthreads();
    }

#pragma unroll
    for (int mi = 0; mi < 4; mi++) {
        int r0 = bm + wm * 64 + mi * 16 + g;
#pragma unroll
        for (int ni = 0; ni < 4; ni++) {
            int cc = bn + wn * 32 + ni * 8 + 2 * tg;
            float b0 = bias[cc] + 1e-6f;
            float b1 = bias[cc + 1] + 1e-6f;
            g_h[(size_t)r0 * DIM + cc]           = c[mi][ni][0] + b0;
            g_h[(size_t)r0 * DIM + cc + 1]       = c[mi][ni][1] + b1;
            g_h[(size_t)(r0 + 8) * DIM + cc]     = c[mi][ni][2] + b0;
            g_h[(size_t)(r0 + 8) * DIM + cc + 1] = c[mi][ni][3] + b1;
        }
    }
}

// ---------------- kernel 3: circuit, 8 amps/thread, 128 threads ----------------
__device__ __forceinline__ void rot1(float2 va, float2 vb, float& r, float& i,
                                     float pr, float pi) {
    float nr = va.x * r - va.y * i + vb.x * pr - vb.y * pi;
    float ni = va.x * i + va.y * r + vb.x * pi + vb.y * pr;
    r = nr; i = ni;
}

__global__ __launch_bounds__(128, 8) void circuit_kernel(const float* __restrict__ Wout,
                                                         const float* __restrict__ bout,
                                                         float* __restrict__ out) {
    __shared__ float4 xchg[640];                 // exchange buf (stride-5 float4) / perm stage
    __shared__ float2 sg[NL * NQ * 4];
    __shared__ float  red[4][9];
    __shared__ float  sevn[NQ];
    float2* stage = (float2*)xchg;               // 1024 float2 = 8KB, fits in xchg

    const int t    = threadIdx.x;
    const int lane = t & 31;
    const int b    = blockIdx.x;

    // amp j = 8*t + a : bits 0-2 local, 3-7 lane, 8-9 warp
    const float* hrow = g_h + (size_t)b * DIM + 8 * t;
    float4 hA = *(const float4*)hrow;
    float4 hB = *(const float4*)(hrow + 4);
    float ar[8] = {hA.x, hA.y, hA.z, hA.w, hB.x, hB.y, hB.z, hB.w};
    float ai[8] = {0.f, 0.f, 0.f, 0.f, 0.f, 0.f, 0.f, 0.f};

    for (int i = t; i < NL * NQ * 4; i += 128) sg[i] = g_gates[i];
    __syncthreads();

    for (int l = 0; l < NL; l++) {
        const float2* gl = sg + l * NQ * 4;

        // w=0,1 -> m=9,8 : smem exchange with thread t^64 / t^32
#pragma unroll
        for (int w = 0; w < 2; w++) {
            const float2 u00 = gl[4 * w + 0], u01 = gl[4 * w + 1];
            const float2 u10 = gl[4 * w + 2], u11 = gl[4 * w + 3];
            const int pmask = w ? 32 : 64;
#pragma unroll
            for (int k = 0; k < 4; k++)
                xchg[t * 5 + k] = make_float4(ar[2 * k], ai[2 * k], ar[2 * k + 1], ai[2 * k + 1]);
            __syncthreads();
            const int pth = t ^ pmask;
            float4 o0 = xchg[pth * 5 + 0];
            float4 o1 = xchg[pth * 5 + 1];
            float4 o2 = xchg[pth * 5 + 2];
            float4 o3 = xchg[pth * 5 + 3];
            __syncthreads();
            const bool hib = (t & pmask) != 0;
            const float2 va = hib ? u11 : u00;
            const float2 vb = hib ? u10 : u01;
            rot1(va, vb, ar[0], ai[0], o0.x, o0.y);
            rot1(va, vb, ar[1], ai[1], o0.z, o0.w);
            rot1(va, vb, ar[2], ai[2], o1.x, o1.y);
            rot1(va, vb, ar[3], ai[3], o1.z, o1.w);
            rot1(va, vb, ar[4], ai[4], o2.x, o2.y);
            rot1(va, vb, ar[5], ai[5], o2.z, o2.w);
            rot1(va, vb, ar[6], ai[6], o3.x, o3.y);
            rot1(va, vb, ar[7], ai[7], o3.z, o3.w);
        }

        // w=2..6 -> m=7..3 : shfl over lane bit (6-w)
#pragma unroll
        for (int w = 2; w < 7; w++) {
            const float2 u00 = gl[4 * w + 0], u01 = gl[4 * w + 1];
            const float2 u10 = gl[4 * w + 2], u11 = gl[4 * w + 3];
            const int msk = 1 << (6 - w);
            const bool hib = (lane & msk) != 0;
            const float2 va = hib ? u11 : u00;
            const float2 vb = hib ? u10 : u01;
#pragma unroll
            for (int a = 0; a < 8; a++) {
                float pr = __shfl_xor_sync(0xffffffffu, ar[a], msk);
                float pi = __shfl_xor_sync(0xffffffffu, ai[a], msk);
                rot1(va, vb, ar[a], ai[a], pr, pi);
            }
        }

        // w=7,8,9 -> m=2,1,0 : local pairs
#pragma unroll
        for (int w = 7; w < 10; w++) {
            const float2 u00 = gl[4 * w + 0], u01 = gl[4 * w + 1];
            const float2 u10 = gl[4 * w + 2], u11 = gl[4 * w + 3];
            const int dm = 1 << (9 - w);
#pragma unroll
            for (int a = 0; a < 8; a++) {
                if (!(a & dm)) {
                    float lr = ar[a], li = ai[a];
                    float hr = ar[a + dm], hi2 = ai[a + dm];
                    ar[a]      = u00.x * lr - u00.y * li + u01.x * hr - u01.y * hi2;
                    ai[a]      = u00.x * li + u00.y * lr + u01.x * hi2 + u01.y * hr;
                    ar[a + dm] = u10.x * lr - u10.y * li + u11.x * hr - u11.y * hi2;
                    ai[a + dm] = u10.x * li + u10.y * lr + u11.x * hi2 + u11.y * hr;
                }
            }
        }

        // layer permutation: psi_new[j] = psi[perm[j]]; stage layout [a-plane][t]
#pragma unroll
        for (int a = 0; a < 8; a++) stage[a * 128 + t] = make_float2(ar[a], ai[a]);
        __syncthreads();
        const int* pm = g_perm + l * DIM + 8 * t;
        int4 pa = *(const int4*)pm;
        int4 pb = *(const int4*)(pm + 4);
        int pp[8] = {pa.x, pa.y, pa.z, pa.w, pb.x, pb.y, pb.z, pb.w};
        float2 nv[8];
#pragma unroll
        for (int a = 0; a < 8; a++) {
            int p = pp[a];
            nv[a] = stage[(p & 7) * 128 + (p >> 3)];
        }
        __syncthreads();
#pragma unroll
        for (int a = 0; a < 8; a++) { ar[a] = nv[a].x; ai[a] = nv[a].y; }
    }

    // expvals (unnormalized; divide by total prob at the end)
    float p[8];
#pragma unroll
    for (int a = 0; a < 8; a++) p[a] = ar[a] * ar[a] + ai[a] * ai[a];
    float ps = ((p[0] + p[1]) + (p[2] + p[3])) + ((p[4] + p[5]) + (p[6] + p[7]));

    float v[9];
    v[0] = ps;
#pragma unroll
    for (int i = 0; i < 5; i++)                              // q = 2+i, lane bit 4-i
        v[1 + i] = ((lane >> (4 - i)) & 1) ? -ps : ps;
    v[6] = ((p[0] + p[1]) + (p[2] + p[3])) - ((p[4] + p[5]) + (p[6] + p[7]));  // q7 (bit2 of a)
    v[7] = ((p[0] + p[1]) + (p[4] + p[5])) - ((p[2] + p[3]) + (p[6] + p[7]));  // q8 (bit1)
    v[8] = ((p[0] + p[2]) + (p[4] + p[6])) - ((p[1] + p[3]) + (p[5] + p[7]));  // q9 (bit0)

#pragma unroll
    for (int j = 0; j < 9; j++) {
#pragma unroll
        for (int o = 16; o; o >>= 1) v[j] += __shfl_xor_sync(0xffffffffu, v[j], o);
    }
    if (lane == 0) {
        int wi = t >> 5;
#pragma unroll
        for (int j = 0; j < 9; j++) red[wi][j] = v[j];
    }
    __syncthreads();

    if (t < NQ) {
        const int q = t;
        float pst = ((red[0][0] + red[1][0]) + (red[2][0] + red[3][0]));
        float e;
        if (q >= 2) {
            e = ((red[0][q - 1] + red[1][q - 1]) + (red[2][q - 1] + red[3][q - 1]));
        } else if (q == 0) {   // j bit9 = warp bit1
            e = (red[0][0] + red[1][0]) - (red[2][0] + red[3][0]);
        } else {               // j bit8 = warp bit0
            e = (red[0][0] - red[1][0]) + (red[2][0] - red[3][0]);
        }
        sevn[q] = e / pst;
    }
    __syncthreads();

    if (t < PRED) {
        float o = bout[t];
#pragma unroll
        for (int q = 0; q < NQ; q++) o += sevn[q] * Wout[t * NQ + q];
        out[(size_t)b * PRED + t] = o;
    }
}

// ---------------- launch ----------------
extern "C" void kernel_launch(void* const* d_in, const int* in_sizes, int n_in,
                              void* d_out, int out_size) {
    const float* x     = (const float*)d_in[0];
    const float* W_in  = (const float*)d_in[1];
    const float* b_in  = (const float*)d_in[2];
    const float* qw    = (const float*)d_in[3];
    const float* W_out = (const float*)d_in[4];
    const float* b_out = (const float*)d_in[5];
    float* out = (float*)d_out;

    split_kernel<<<(BATCH * SEQ + 255) / 256, 256>>>(x, W_in);
    precompute_kernel<<<1, 1024>>>(qw);
    dim3 grid(DIM / GBN, BATCH / GBM);
    gemm_tc<<<grid, 256>>>(b_in);
    circuit_kernel<<<BATCH, 128>>>(W_out, b_out, out);
}

// round 7
// speedup vs baseline: 3.6152x; 1.0287x over previous
#include <cuda_runtime.h>
#include <cuda_bf16.h>
#include <cstdint>

#define NQ    10
#define DIM   1024
#define NL    4
#define BATCH 4096
#define SEQ   512
#define PRED  96

// ---------------- device scratch (allocation-free) ----------------
__device__ float         g_h[BATCH * DIM];       // 16 MB intermediate h
__device__ __nv_bfloat16 g_xhi[BATCH * SEQ];
__device__ __nv_bfloat16 g_xlo[BATCH * SEQ];
__device__ __nv_bfloat16 g_whi[DIM * SEQ];
__device__ __nv_bfloat16 g_wlo[DIM * SEQ];
__device__ float2        g_gates[NL * NQ * 4];
__device__ int           g_perm[NL * DIM];

// ---------------- kernel 0: bf16 hi/lo split of x and W ----------------
__global__ void split_kernel(const float* __restrict__ x, const float* __restrict__ w) {
    int i = blockIdx.x * blockDim.x + threadIdx.x;
    if (i < BATCH * SEQ) {
        float v = x[i];
        __nv_bfloat16 h = __float2bfloat16(v);
        g_xhi[i] = h;
        g_xlo[i] = __float2bfloat16(v - __bfloat162float(h));
    }
    if (i < DIM * SEQ) {
        float v = w[i];
        __nv_bfloat16 h = __float2bfloat16(v);
        g_whi[i] = h;
        g_wlo[i] = __float2bfloat16(v - __bfloat162float(h));
    }
}

// ---------------- kernel 1: precompute gates + perms ----------------
__global__ void precompute_kernel(const float* __restrict__ qw) {
    int t = threadIdx.x;
    if (t < NL * NQ) {
        float phi   = qw[3 * t + 0];
        float theta = qw[3 * t + 1];
        float omega = qw[3 * t + 2];
        float s, c;
        sincosf(0.5f * theta, &s, &c);
        float a = 0.5f * (phi + omega);
        float b = 0.5f * (phi - omega);
        float sa, ca, sb, cb;
        sincosf(a, &sa, &ca);
        sincosf(b, &sb, &cb);
        g_gates[4 * t + 0] = make_float2( c * ca, -c * sa);
        g_gates[4 * t + 1] = make_float2(-s * cb, -s * sb);
        g_gates[4 * t + 2] = make_float2( s * cb, -s * sb);
        g_gates[4 * t + 3] = make_float2( c * ca,  c * sa);
    }
    if (t < DIM) {
        for (int l = 0; l < NL; l++) {
            int r = l % (NQ - 1) + 1;
            int p = t;
            for (int c = NQ - 1; c >= 0; c--) {
                int bit = (p >> (NQ - 1 - c)) & 1;
                int tgt = (c + r) % NQ;
                p ^= bit << (NQ - 1 - tgt);
            }
            g_perm[l * DIM + t] = p;
        }
    }
}

// ---------------- kernel 2: bf16 tensor-core GEMM (3-product) ----------------
#define GBM 128
#define GBN 128
#define GBK 16
#define SROW 24                 // bf16 per smem row (16 + 8 pad) = 48 bytes
#define MATB (GBM * SROW * 2)   // bytes per matrix tile = 6144
#define STAGEB (4 * MATB)       // bytes per stage = 24576

#define MMA_BF16(C, A, B)                                                       \
    asm volatile("mma.sync.aligned.m16n8k16.row.col.f32.bf16.bf16.f32 "         \
                 "{%0,%1,%2,%3}, {%4,%5,%6,%7}, {%8,%9}, {%0,%1,%2,%3};"        \
                 : "+f"((C)[0]), "+f"((C)[1]), "+f"((C)[2]), "+f"((C)[3])       \
                 : "r"((A)[0]), "r"((A)[1]), "r"((A)[2]), "r"((A)[3]),          \
                   "r"((B)[0]), "r"((B)[1]))

#define LDM4(R, addr)                                                           \
    asm volatile("ldmatrix.sync.aligned.m8n8.x4.shared.b16 {%0,%1,%2,%3},[%4];" \
                 : "=r"((R)[0]), "=r"((R)[1]), "=r"((R)[2]), "=r"((R)[3])       \
                 : "r"(addr))

#define CPASYNC16(dst, src)                                                     \
    asm volatile("cp.async.cg.shared.global [%0], [%1], 16;" ::                 \
                 "r"(dst), "l"(src))

__global__ __launch_bounds__(256) void gemm_tc(const float* __restrict__ bias) {
    __shared__ __nv_bfloat16 smem[2 * 4 * GBM * SROW];   // 49152 bytes
    const int tid  = threadIdx.x;
    const int lane = tid & 31, wid = tid >> 5;
    const int wm = wid >> 2, wn = wid & 3;               // 2(m) x 4(n) warps; warp tile 64x32
    const int bm = blockIdx.y * GBM, bn = blockIdx.x * GBN;
    const int g = lane >> 2, tg = lane & 3;

    const uint32_t sbase = (uint32_t)__cvta_generic_to_shared(smem);

    float c[4][4][4];
#pragma unroll
    for (int mi = 0; mi < 4; mi++)
#pragma unroll
        for (int ni = 0; ni < 4; ni++)
#pragma unroll
            for (int k = 0; k < 4; k++) c[mi][ni][k] = 0.f;

    // loader indexing: 256 threads, each does one 16B chunk per matrix
    const int lr = tid >> 1, lc = tid & 1;
    const size_t offA = (size_t)(bm + lr) * SEQ + lc * 8;
    const size_t offB = (size_t)(bn + lr) * SEQ + lc * 8;
    const uint32_t ldst = (uint32_t)(lr * SROW + lc * 8) * 2;

    auto load_stage = [&](int st, int k0) {
        uint32_t d = sbase + st * STAGEB + ldst;
        CPASYNC16(d + 0 * MATB, g_xhi + offA + k0);
        CPASYNC16(d + 1 * MATB, g_xlo + offA + k0);
        CPASYNC16(d + 2 * MATB, g_whi + offB + k0);
        CPASYNC16(d + 3 * MATB, g_wlo + offB + k0);
        asm volatile("cp.async.commit_group;");
    };

    const int rA   = (lane & 7) + ((lane >> 3) & 1) * 8;
    const int colo = (lane >> 4) * 16;

    load_stage(0, 0);
    const int NIT = SEQ / GBK;
    for (int it = 0; it < NIT; it++) {
        if (it + 1 < NIT) {
            load_stage((it + 1) & 1, (it + 1) * GBK);
            asm volatile("cp.async.wait_group 1;");
        } else {
            asm volatile("cp.async.wait_group 0;");
        }
        __syncthreads();

        const uint32_t st = sbase + (it & 1) * STAGEB;
        unsigned ah[4][4], al[4][4], bh[4][2], bl[4][2];
#pragma unroll
        for (int mi = 0; mi < 4; mi++) {
            uint32_t ad = st + (uint32_t)((wm * 64 + mi * 16 + rA) * SROW) * 2 + colo;
            LDM4(ah[mi], ad);
            LDM4(al[mi], ad + MATB);
        }
#pragma unroll
        for (int nj = 0; nj < 2; nj++) {
            uint32_t bd = st + 2 * MATB + (uint32_t)((wn * 32 + nj * 16 + rA) * SROW) * 2 + colo;
            unsigned r[4];
            LDM4(r, bd);
            bh[2 * nj][0] = r[0]; bh[2 * nj + 1][0] = r[1];
            bh[2 * nj][1] = r[2]; bh[2 * nj + 1][1] = r[3];
            LDM4(r, bd + MATB);
            bl[2 * nj][0] = r[0]; bl[2 * nj + 1][0] = r[1];
            bl[2 * nj][1] = r[2]; bl[2 * nj + 1][1] = r[3];
        }
#pragma unroll
        for (int mi = 0; mi < 4; mi++)
#pragma unroll
            for (int ni = 0; ni < 4; ni++) {
                MMA_BF16(c[mi][ni], ah[mi], bh[ni]);
                MMA_BF16(c[mi][ni], ah[mi], bl[ni]);
                MMA_BF16(c[mi][ni], al[mi], bh[ni]);
            }
        __syncthreads();
    }

#pragma unroll
    for (int mi = 0; mi < 4; mi++) {
        int r0 = bm + wm * 64 + mi * 16 + g;
#pragma unroll
        for (int ni = 0; ni < 4; ni++) {
            int cc = bn + wn * 32 + ni * 8 + 2 * tg;
            float b0 = bias[cc] + 1e-6f;
            float b1 = bias[cc + 1] + 1e-6f;
            g_h[(size_t)r0 * DIM + cc]           = c[mi][ni][0] + b0;
            g_h[(size_t)r0 * DIM + cc + 1]       = c[mi][ni][1] + b1;
            g_h[(size_t)(r0 + 8) * DIM + cc]     = c[mi][ni][2] + b0;
            g_h[(size_t)(r0 + 8) * DIM + cc + 1] = c[mi][ni][3] + b1;
        }
    }
}

// ---------------- kernel 3: circuit, 8 amps/thread, 128 threads ----------------
__device__ __forceinline__ void rot1(float2 va, float2 vb, float& r, float& i,
                                     float pr, float pi) {
    float nr = va.x * r - va.y * i + vb.x * pr - vb.y * pi;
    float ni = va.x * i + va.y * r + vb.x * pi + vb.y * pr;
    r = nr; i = ni;
}

__global__ __launch_bounds__(128, 8) void circuit_kernel(const float* __restrict__ Wout,
                                                         const float* __restrict__ bout,
                                                         float* __restrict__ out) {
    __shared__ float4 xchg[640];                 // exchange buf (stride-5 float4) / perm stage
    __shared__ float2 sg[NL * NQ * 4];
    __shared__ float  red[4][9];
    __shared__ float  sevn[NQ];
    float2* stage = (float2*)xchg;               // 1024 float2 = 8KB, fits in xchg

    const int t    = threadIdx.x;
    const int lane = t & 31;
    const int b    = blockIdx.x;

    // amp j = 8*t + a : bits 0-2 local, 3-7 lane, 8-9 warp
    const float* hrow = g_h + (size_t)b * DIM + 8 * t;
    float4 hA = *(const float4*)hrow;
    float4 hB = *(const float4*)(hrow + 4);
    float ar[8] = {hA.x, hA.y, hA.z, hA.w, hB.x, hB.y, hB.z, hB.w};
    float ai[8] = {0.f, 0.f, 0.f, 0.f, 0.f, 0.f, 0.f, 0.f};

    for (int i = t; i < NL * NQ * 4; i += 128) sg[i] = g_gates[i];
    __syncthreads();

    for (int l = 0; l < NL; l++) {
        const float2* gl = sg + l * NQ * 4;

        // w=0,1 -> m=9,8 : smem exchange with thread t^64 / t^32
#pragma unroll
        for (int w = 0; w < 2; w++) {
            const float2 u00 = gl[4 * w + 0], u01 = gl[4 * w + 1];
            const float2 u10 = gl[4 * w + 2], u11 = gl[4 * w + 3];
            const int pmask = w ? 32 : 64;
#pragma unroll
            for (int k = 0; k < 4; k++)
                xchg[t * 5 + k] = make_float4(ar[2 * k], ai[2 * k], ar[2 * k + 1], ai[2 * k + 1]);
            __syncthreads();
            const int pth = t ^ pmask;
            float4 o0 = xchg[pth * 5 + 0];
            float4 o1 = xchg[pth * 5 + 1];
            float4 o2 = xchg[pth * 5 + 2];
            float4 o3 = xchg[pth * 5 + 3];
            __syncthreads();
            const bool hib = (t & pmask) != 0;
            const float2 va = hib ? u11 : u00;
            const float2 vb = hib ? u10 : u01;
            rot1(va, vb, ar[0], ai[0], o0.x, o0.y);
            rot1(va, vb, ar[1], ai[1], o0.z, o0.w);
            rot1(va, vb, ar[2], ai[2], o1.x, o1.y);
            rot1(va, vb, ar[3], ai[3], o1.z, o1.w);
            rot1(va, vb, ar[4], ai[4], o2.x, o2.y);
            rot1(va, vb, ar[5], ai[5], o2.z, o2.w);
            rot1(va, vb, ar[6], ai[6], o3.x, o3.y);
            rot1(va, vb, ar[7], ai[7], o3.z, o3.w);
        }

        // w=2..6 -> m=7..3 : shfl over lane bit (6-w)
#pragma unroll
        for (int w = 2; w < 7; w++) {
            const float2 u00 = gl[4 * w + 0], u01 = gl[4 * w + 1];
            const float2 u10 = gl[4 * w + 2], u11 = gl[4 * w + 3];
            const int msk = 1 << (6 - w);
            const bool hib = (lane & msk) != 0;
            const float2 va = hib ? u11 : u00;
            const float2 vb = hib ? u10 : u01;
#pragma unroll
            for (int a = 0; a < 8; a++) {
                float pr = __shfl_xor_sync(0xffffffffu, ar[a], msk);
                float pi = __shfl_xor_sync(0xffffffffu, ai[a], msk);
                rot1(va, vb, ar[a], ai[a], pr, pi);
            }
        }

        // w=7,8,9 -> m=2,1,0 : local pairs
#pragma unroll
        for (int w = 7; w < 10; w++) {
            const float2 u00 = gl[4 * w + 0], u01 = gl[4 * w + 1];
            const float2 u10 = gl[4 * w + 2], u11 = gl[4 * w + 3];
            const int dm = 1 << (9 - w);
#pragma unroll
            for (int a = 0; a < 8; a++) {
                if (!(a & dm)) {
                    float lr = ar[a], li = ai[a];
                    float hr = ar[a + dm], hi2 = ai[a + dm];
                    ar[a]      = u00.x * lr - u00.y * li + u01.x * hr - u01.y * hi2;
                    ai[a]      = u00.x * li + u00.y * lr + u01.x * hi2 + u01.y * hr;
                    ar[a + dm] = u10.x * lr - u10.y * li + u11.x * hr - u11.y * hi2;
                    ai[a + dm] = u10.x * li + u10.y * lr + u11.x * hi2 + u11.y * hr;
                }
            }
        }

        // layer permutation: psi_new[j] = psi[perm[j]]; stage layout [a-plane][t]
#pragma unroll
        for (int a = 0; a < 8; a++) stage[a * 128 + t] = make_float2(ar[a], ai[a]);
        __syncthreads();
        const int* pm = g_perm + l * DIM + 8 * t;
        int4 pa = *(const int4*)pm;
        int4 pb = *(const int4*)(pm + 4);
        int pp[8] = {pa.x, pa.y, pa.z, pa.w, pb.x, pb.y, pb.z, pb.w};
        float2 nv[8];
#pragma unroll
        for (int a = 0; a < 8; a++) {
            int p = pp[a];
            nv[a] = stage[(p & 7) * 128 + (p >> 3)];
        }
        __syncthreads();
#pragma unroll
        for (int a = 0; a < 8; a++) { ar[a] = nv[a].x; ai[a] = nv[a].y; }
    }

    // expvals (unnormalized; divide by total prob at the end)
    float p[8];
#pragma unroll
    for (int a = 0; a < 8; a++) p[a] = ar[a] * ar[a] + ai[a] * ai[a];
    float ps = ((p[0] + p[1]) + (p[2] + p[3])) + ((p[4] + p[5]) + (p[6] + p[7]));

    float v[9];
    v[0] = ps;
#pragma unroll
    for (int i = 0; i < 5; i++)                              // q = 2+i, lane bit 4-i
        v[1 + i] = ((lane >> (4 - i)) & 1) ? -ps : ps;
    v[6] = ((p[0] + p[1]) + (p[2] + p[3])) - ((p[4] + p[5]) + (p[6] + p[7]));  // q7 (bit2 of a)
    v[7] = ((p[0] + p[1]) + (p[4] + p[5])) - ((p[2] + p[3]) + (p[6] + p[7]));  // q8 (bit1)
    v[8] = ((p[0] + p[2]) + (p[4] + p[6])) - ((p[1] + p[3]) + (p[5] + p[7]));  // q9 (bit0)

#pragma unroll
    for (int j = 0; j < 9; j++) {
#pragma unroll
        for (int o = 16; o; o >>= 1) v[j] += __shfl_xor_sync(0xffffffffu, v[j], o);
    }
    if (lane == 0) {
        int wi = t >> 5;
#pragma unroll
        for (int j = 0; j < 9; j++) red[wi][j] = v[j];
    }
    __syncthreads();

    if (t < NQ) {
        const int q = t;
        float pst = ((red[0][0] + red[1][0]) + (red[2][0] + red[3][0]));
        float e;
        if (q >= 2) {
            e = ((red[0][q - 1] + red[1][q - 1]) + (red[2][q - 1] + red[3][q - 1]));
        } else if (q == 0) {   // j bit9 = warp bit1
            e = (red[0][0] + red[1][0]) - (red[2][0] + red[3][0]);
        } else {               // j bit8 = warp bit0
            e = (red[0][0] - red[1][0]) + (red[2][0] - red[3][0]);
        }
        sevn[q] = e / pst;
    }
    __syncthreads();

    if (t < PRED) {
        float o = bout[t];
#pragma unroll
        for (int q = 0; q < NQ; q++) o += sevn[q] * Wout[t * NQ + q];
        out[(size_t)b * PRED + t] = o;
    }
}

// ---------------- launch ----------------
extern "C" void kernel_launch(void* const* d_in, const int* in_sizes, int n_in,
                              void* d_out, int out_size) {
    const float* x     = (const float*)d_in[0];
    const float* W_in  = (const float*)d_in[1];
    const float* b_in  = (const float*)d_in[2];
    const float* qw    = (const float*)d_in[3];
    const float* W_out = (const float*)d_in[4];
    const float* b_out = (const float*)d_in[5];
    float* out = (float*)d_out;

    split_kernel<<<(BATCH * SEQ + 255) / 256, 256>>>(x, W_in);
    precompute_kernel<<<1, 1024>>>(qw);
    dim3 grid(DIM / GBN, BATCH / GBM);
    gemm_tc<<<grid, 256>>>(b_in);
    circuit_kernel<<<BATCH, 128>>>(W_out, b_out, out);
}